// round 1
// baseline (speedup 1.0000x reference)
#include <cuda_runtime.h>

#define T_TOK 8192
#define DIM   1024
#define FFD   4096
#define NEXP  8

// ---- scratch (static device globals; no allocations) ----
__device__ int   g_count[NEXP];
__device__ int   g_offset[NEXP];
__device__ int   g_tok[NEXP * T_TOK];
__device__ float g_gate[NEXP * T_TOK];
__device__ float g_h[(size_t)T_TOK * 2 * FFD];   // 268 MB scratch for h

__device__ __forceinline__ float tf32r(float x) {
    float y;
    asm("cvt.rna.tf32.f32 %0, %1;" : "=f"(y) : "f"(x));
    return y;
}

__device__ __forceinline__ void mma_tf32(float c[4], const unsigned a[4], const unsigned b[2]) {
    asm volatile(
        "mma.sync.aligned.m16n8k8.row.col.f32.tf32.tf32.f32 "
        "{%0,%1,%2,%3}, {%4,%5,%6,%7}, {%8,%9}, {%0,%1,%2,%3};"
        : "+f"(c[0]), "+f"(c[1]), "+f"(c[2]), "+f"(c[3])
        : "r"(a[0]), "r"(a[1]), "r"(a[2]), "r"(a[3]), "r"(b[0]), "r"(b[1]));
}

// ---- zero output + routing counters ----
__global__ void k_zero(float* p, int n) {
    int i = blockIdx.x * blockDim.x + threadIdx.x;
    if (i < n) p[i] = 0.f;
    if (blockIdx.x == 0 && threadIdx.x < NEXP) g_count[threadIdx.x] = 0;
}

// ---- gating: one warp per token ----
__global__ void k_gate(const float* __restrict__ x, const float* __restrict__ wg,
                       const float* __restrict__ bg, float* __restrict__ out, int has_tail) {
    __shared__ float s_wg[NEXP * DIM];
    __shared__ float s_bg[NEXP];
    int tid = threadIdx.x;
    for (int i = tid; i < NEXP * DIM; i += 256) s_wg[i] = wg[i];
    if (tid < NEXP) s_bg[tid] = bg[tid];
    __syncthreads();

    int warp = tid >> 5, lane = tid & 31;
    int t = blockIdx.x * 8 + warp;
    const float* xr = x + (size_t)t * DIM;

    float acc[NEXP];
#pragma unroll
    for (int e = 0; e < NEXP; e++) acc[e] = 0.f;
    for (int d = lane; d < DIM; d += 32) {
        float xv = xr[d];
#pragma unroll
        for (int e = 0; e < NEXP; e++) acc[e] += xv * s_wg[e * DIM + d];
    }
#pragma unroll
    for (int e = 0; e < NEXP; e++) {
#pragma unroll
        for (int o = 16; o > 0; o >>= 1) acc[e] += __shfl_xor_sync(0xffffffffu, acc[e], o);
    }

    if (lane == 0) {
        float p[NEXP];
        float m = -1e30f;
#pragma unroll
        for (int e = 0; e < NEXP; e++) { p[e] = acc[e] + s_bg[e]; m = fmaxf(m, p[e]); }
        float s = 0.f;
#pragma unroll
        for (int e = 0; e < NEXP; e++) { p[e] = expf(p[e] - m); s += p[e]; }
        float inv = 1.f / s;
#pragma unroll
        for (int e = 0; e < NEXP; e++) p[e] *= inv;

        // top-2, ties -> lowest index (strict >)
        int e1 = 0;
#pragma unroll
        for (int e = 1; e < NEXP; e++) if (p[e] > p[e1]) e1 = e;
        int e2 = (e1 == 0) ? 1 : 0;
#pragma unroll
        for (int e = 0; e < NEXP; e++) if (e != e1 && p[e] > p[e2]) e2 = e;

        int pos1 = atomicAdd(&g_count[e1], 1);
        g_tok[e1 * T_TOK + pos1]  = t;
        g_gate[e1 * T_TOK + pos1] = p[e1];
        int pos2 = atomicAdd(&g_count[e2], 1);
        g_tok[e2 * T_TOK + pos2]  = t;
        g_gate[e2 * T_TOK + pos2] = p[e2];

        if (has_tail) {
            float* tail = out + (size_t)T_TOK * DIM;
            tail[t * 2 + 0] = (float)e1;
            tail[t * 2 + 1] = (float)e2;
            tail[T_TOK * 2 + t * 2 + 0] = p[e1];
            tail[T_TOK * 2 + t * 2 + 1] = p[e2];
        }
    }
}

__global__ void k_offsets() {
    int s = 0;
    for (int e = 0; e < NEXP; e++) { g_offset[e] = s; s += g_count[e]; }
}

// ---- grouped GEMM: C[m,n] = sum_k A[m,k] * W[n,k], TF32 mma ----
// MODE 0: A = gathered x rows, W = w1[e], epilogue leaky(+b1) -> g_h
// MODE 1: A = g_h rows,        W = w2[e], epilogue (+b2)*gate -> atomic out
template <int MODE>
__global__ void __launch_bounds__(256)
k_gemm(const float* __restrict__ X, const float* __restrict__ W,
       const float* __restrict__ bias, float* __restrict__ out) {
    constexpr int KD = (MODE == 0) ? DIM : FFD;
    constexpr int ND = (MODE == 0) ? FFD : DIM;

    int e = blockIdx.z;
    int cnt = g_count[e];
    int m0 = blockIdx.y * 128;
    if (m0 >= cnt) return;
    int n0 = blockIdx.x * 64;
    int off = g_offset[e];

    __shared__ __align__(16) float As[128 * 36];
    __shared__ __align__(16) float Bs[64 * 36];
    __shared__ int   s_tok[128];
    __shared__ float s_gate[128];

    int tid = threadIdx.x;
    for (int r = tid; r < 128; r += 256) {
        int mc = min(m0 + r, cnt - 1);
        s_tok[r]  = g_tok[e * T_TOK + mc];
        s_gate[r] = g_gate[e * T_TOK + mc];
    }
    __syncthreads();

    const float* Wb = W + (size_t)e * ND * KD;

    float c[2][4][4];
#pragma unroll
    for (int i = 0; i < 2; i++)
#pragma unroll
        for (int j = 0; j < 4; j++)
#pragma unroll
            for (int q = 0; q < 4; q++) c[i][j][q] = 0.f;

    int warp = tid >> 5, lane = tid & 31;
    int g = lane >> 2, tg = lane & 3;
    int wm = (warp & 3) * 32, wn = (warp >> 2) * 32;

    for (int k0 = 0; k0 < KD; k0 += 32) {
        // A tile: 128 x 32
#pragma unroll
        for (int it = 0; it < 4; it++) {
            int idx = tid + it * 256;
            int r = idx >> 3, c4 = (idx & 7) << 2;
            const float* src;
            if (MODE == 0) {
                src = X + (size_t)s_tok[r] * DIM + (k0 + c4);
            } else {
                int ar = off + min(m0 + r, cnt - 1);
                src = g_h + (size_t)ar * FFD + (k0 + c4);
            }
            float4 v = *(const float4*)src;
            float4 w;
            w.x = tf32r(v.x); w.y = tf32r(v.y); w.z = tf32r(v.z); w.w = tf32r(v.w);
            *(float4*)&As[r * 36 + c4] = w;
        }
        // B tile: 64 x 32
#pragma unroll
        for (int it = 0; it < 2; it++) {
            int idx = tid + it * 256;
            int r = idx >> 3, c4 = (idx & 7) << 2;
            float4 v = *(const float4*)(Wb + (size_t)(n0 + r) * KD + (k0 + c4));
            float4 w;
            w.x = tf32r(v.x); w.y = tf32r(v.y); w.z = tf32r(v.z); w.w = tf32r(v.w);
            *(float4*)&Bs[r * 36 + c4] = w;
        }
        __syncthreads();

#pragma unroll
        for (int kk = 0; kk < 4; kk++) {
            int kb = kk * 8;
            unsigned a[2][4], b[4][2];
#pragma unroll
            for (int mi = 0; mi < 2; mi++) {
                int row = wm + mi * 16;
                a[mi][0] = __float_as_uint(As[(row + g) * 36 + kb + tg]);
                a[mi][1] = __float_as_uint(As[(row + g + 8) * 36 + kb + tg]);
                a[mi][2] = __float_as_uint(As[(row + g) * 36 + kb + tg + 4]);
                a[mi][3] = __float_as_uint(As[(row + g + 8) * 36 + kb + tg + 4]);
            }
#pragma unroll
            for (int nj = 0; nj < 4; nj++) {
                int col = wn + nj * 8;
                b[nj][0] = __float_as_uint(Bs[(col + g) * 36 + kb + tg]);
                b[nj][1] = __float_as_uint(Bs[(col + g) * 36 + kb + tg + 4]);
            }
#pragma unroll
            for (int mi = 0; mi < 2; mi++)
#pragma unroll
                for (int nj = 0; nj < 4; nj++)
                    mma_tf32(c[mi][nj], a[mi], b[nj]);
        }
        __syncthreads();
    }

    // epilogue
#pragma unroll
    for (int mi = 0; mi < 2; mi++) {
#pragma unroll
        for (int rr = 0; rr < 2; rr++) {
            int mloc = wm + mi * 16 + g + rr * 8;
            int mglob = m0 + mloc;
            if (mglob >= cnt) continue;
#pragma unroll
            for (int nj = 0; nj < 4; nj++) {
#pragma unroll
                for (int cc = 0; cc < 2; cc++) {
                    int n = n0 + wn + nj * 8 + 2 * tg + cc;
                    float v = c[mi][nj][rr * 2 + cc] + bias[e * ND + n];
                    if (MODE == 0) {
                        v = (v > 0.f) ? v : 0.1f * v;
                        g_h[(size_t)(off + mglob) * FFD + n] = v;
                    } else {
                        v *= s_gate[mloc];
                        atomicAdd(&out[(size_t)s_tok[mloc] * DIM + n], v);
                    }
                }
            }
        }
    }
}

extern "C" void kernel_launch(void* const* d_in, const int* in_sizes, int n_in,
                              void* d_out, int out_size) {
    const float* x  = (const float*)d_in[0];
    const float* wg = (const float*)d_in[1];
    const float* bg = (const float*)d_in[2];
    const float* w1 = (const float*)d_in[3];
    const float* b1 = (const float*)d_in[4];
    const float* w2 = (const float*)d_in[5];
    const float* b2 = (const float*)d_in[6];
    float* out = (float*)d_out;

    const int base = T_TOK * DIM;
    int has_tail = (out_size >= base + 4 * T_TOK) ? 1 : 0;

    k_zero<<<(out_size + 255) / 256, 256>>>(out, out_size);
    k_gate<<<T_TOK / 8, 256>>>(x, wg, bg, out, has_tail);
    k_offsets<<<1, 1>>>();
    k_gemm<0><<<dim3(FFD / 64, T_TOK / 128, NEXP), 256>>>(x, w1, b1, nullptr);
    k_gemm<1><<<dim3(DIM / 64, T_TOK / 128, NEXP), 256>>>(nullptr, w2, b2, out);
}

// round 2
// speedup vs baseline: 1.4850x; 1.4850x over previous
#include <cuda_runtime.h>

#define T_TOK 8192
#define DIM   1024
#define FFD   4096
#define NEXP  8

// ---- static device scratch (no allocations) ----
__device__ int   g_count[NEXP];
__device__ int   g_offset[NEXP];
__device__ int   g_tok[NEXP * T_TOK];
__device__ float g_gate[NEXP * T_TOK];
__device__ float g_xr[(size_t)T_TOK * DIM];            // tf32-rounded x
__device__ float g_w1r[(size_t)NEXP * FFD * DIM];      // tf32-rounded w1
__device__ float g_w2r[(size_t)NEXP * DIM * FFD];      // tf32-rounded w2
__device__ float g_h[(size_t)T_TOK * 2 * FFD];         // h scratch (tf32-rounded)

// round-to-nearest-away tf32 via integer trick (ALU pipe, matches cvt.rna)
__device__ __forceinline__ float rtf(float x) {
    unsigned u = __float_as_uint(x);
    u = (u + 0x1000u) & 0xFFFFE000u;
    return __uint_as_float(u);
}

__device__ __forceinline__ void mma_tf32(float c[4], const unsigned a[4], const unsigned b[2]) {
    asm volatile(
        "mma.sync.aligned.m16n8k8.row.col.f32.tf32.tf32.f32 "
        "{%0,%1,%2,%3}, {%4,%5,%6,%7}, {%8,%9}, {%0,%1,%2,%3};"
        : "+f"(c[0]), "+f"(c[1]), "+f"(c[2]), "+f"(c[3])
        : "r"(a[0]), "r"(a[1]), "r"(a[2]), "r"(a[3]), "r"(b[0]), "r"(b[1]));
}

__device__ __forceinline__ void cpa16(unsigned dst, const void* src) {
    asm volatile("cp.async.cg.shared.global [%0], [%1], 16;" :: "r"(dst), "l"(src) : "memory");
}

// ---- zero output + routing counters ----
__global__ void k_zero(float* p, int n) {
    int i = blockIdx.x * blockDim.x + threadIdx.x;
    if (i < n) p[i] = 0.f;
    if (blockIdx.x == 0 && threadIdx.x < NEXP) g_count[threadIdx.x] = 0;
}

// ---- tf32 pre-round pass (float4, memory-bound) ----
__global__ void k_round(const float4* __restrict__ in, float4* __restrict__ out, int n4) {
    int i = blockIdx.x * blockDim.x + threadIdx.x;
    if (i < n4) {
        float4 v = in[i];
        v.x = rtf(v.x); v.y = rtf(v.y); v.z = rtf(v.z); v.w = rtf(v.w);
        out[i] = v;
    }
}

// ---- gating: one warp per token ----
__global__ void k_gate(const float* __restrict__ x, const float* __restrict__ wg,
                       const float* __restrict__ bg, float* __restrict__ out, int has_tail) {
    __shared__ float s_wg[NEXP * DIM];
    __shared__ float s_bg[NEXP];
    int tid = threadIdx.x;
    for (int i = tid; i < NEXP * DIM; i += 256) s_wg[i] = wg[i];
    if (tid < NEXP) s_bg[tid] = bg[tid];
    __syncthreads();

    int warp = tid >> 5, lane = tid & 31;
    int t = blockIdx.x * 8 + warp;
    const float* xr = x + (size_t)t * DIM;

    float acc[NEXP];
#pragma unroll
    for (int e = 0; e < NEXP; e++) acc[e] = 0.f;
    for (int d = lane; d < DIM; d += 32) {
        float xv = xr[d];
#pragma unroll
        for (int e = 0; e < NEXP; e++) acc[e] += xv * s_wg[e * DIM + d];
    }
#pragma unroll
    for (int e = 0; e < NEXP; e++) {
#pragma unroll
        for (int o = 16; o > 0; o >>= 1) acc[e] += __shfl_xor_sync(0xffffffffu, acc[e], o);
    }

    if (lane == 0) {
        float p[NEXP];
        float m = -1e30f;
#pragma unroll
        for (int e = 0; e < NEXP; e++) { p[e] = acc[e] + s_bg[e]; m = fmaxf(m, p[e]); }
        float s = 0.f;
#pragma unroll
        for (int e = 0; e < NEXP; e++) { p[e] = expf(p[e] - m); s += p[e]; }
        float inv = 1.f / s;
#pragma unroll
        for (int e = 0; e < NEXP; e++) p[e] *= inv;

        int e1 = 0;
#pragma unroll
        for (int e = 1; e < NEXP; e++) if (p[e] > p[e1]) e1 = e;
        int e2 = (e1 == 0) ? 1 : 0;
#pragma unroll
        for (int e = 0; e < NEXP; e++) if (e != e1 && p[e] > p[e2]) e2 = e;

        int pos1 = atomicAdd(&g_count[e1], 1);
        g_tok[e1 * T_TOK + pos1]  = t;
        g_gate[e1 * T_TOK + pos1] = p[e1];
        int pos2 = atomicAdd(&g_count[e2], 1);
        g_tok[e2 * T_TOK + pos2]  = t;
        g_gate[e2 * T_TOK + pos2] = p[e2];

        if (has_tail) {
            float* tail = out + (size_t)T_TOK * DIM;
            tail[t * 2 + 0] = (float)e1;
            tail[t * 2 + 1] = (float)e2;
            tail[T_TOK * 2 + t * 2 + 0] = p[e1];
            tail[T_TOK * 2 + t * 2 + 1] = p[e2];
        }
    }
}

__global__ void k_offsets() {
    int s = 0;
    for (int e = 0; e < NEXP; e++) { g_offset[e] = s; s += g_count[e]; }
}

// ---- grouped GEMM, 128x128 CTA tile, BK=32, 3-stage cp.async pipeline ----
// MODE 0: A = gathered g_xr rows, W = g_w1r, epilogue leaky(+b1) -> g_h (tf32-rounded)
// MODE 1: A = g_h rows,           W = g_w2r, epilogue (+b2)*gate -> atomic out
// Smem layout per stage: A 128x32 floats then B 128x32 floats; 16B chunks
// swizzled by chunk' = chunk ^ ((row&1)<<2) for conflict-free float4 access.
template <int MODE>
__global__ void __launch_bounds__(256, 1)
k_gemm(const float* __restrict__ bias, float* __restrict__ out) {
    constexpr int KD = (MODE == 0) ? DIM : FFD;
    constexpr int ND = (MODE == 0) ? FFD : DIM;
    constexpr int KT = KD / 32;

    int e = blockIdx.z;
    int cnt = g_count[e];
    int m0 = blockIdx.y * 128;
    if (m0 >= cnt) return;
    int n0 = blockIdx.x * 128;
    int off = g_offset[e];

    extern __shared__ float sm[];            // 3*8192 stage floats + 384 meta
    int*   s_tok  = (int*)(sm + 24576);
    float* s_gate = sm + 24576 + 128;
    float* s_bias = sm + 24576 + 256;

    int tid = threadIdx.x;
    if (tid < 128) {
        int mc = min(m0 + tid, cnt - 1);
        s_tok[tid]  = g_tok[e * T_TOK + mc];
        s_gate[tid] = g_gate[e * T_TOK + mc];
        s_bias[tid] = bias[(size_t)e * ND + n0 + tid];
    }
    __syncthreads();

    const float* Wb = ((MODE == 0) ? g_w1r : g_w2r) + (size_t)e * ND * KD;

    // loader mapping: 8 threads per row, 16B chunk each; 4 rows per thread
    int lr = tid >> 3;
    int lc = tid & 7;
    const float* a_src[4];
    const float* b_src[4];
#pragma unroll
    for (int i = 0; i < 4; i++) {
        int r = lr + 32 * i;
        if (MODE == 0)
            a_src[i] = g_xr + (size_t)s_tok[r] * DIM + lc * 4;
        else
            a_src[i] = g_h + (size_t)(off + min(m0 + r, cnt - 1)) * FFD + lc * 4;
        b_src[i] = Wb + (size_t)(n0 + r) * KD + lc * 4;
    }
    unsigned sm_u32 = (unsigned)__cvta_generic_to_shared(sm);
    unsigned soff = (unsigned)(lr * 128 + ((lc ^ ((lr & 1) << 2)) << 4)); // bytes in stage-A

    auto issue = [&](int st, int k0) {
        unsigned abase = sm_u32 + st * 32768 + soff;
#pragma unroll
        for (int i = 0; i < 4; i++) cpa16(abase + i * 4096, a_src[i] + k0);
        unsigned bbase = abase + 16384;
#pragma unroll
        for (int i = 0; i < 4; i++) cpa16(bbase + i * 4096, b_src[i] + k0);
    };

    int warp = tid >> 5, lane = tid & 31;
    int g = lane >> 2, tg = lane & 3;
    int wm = (warp & 3) * 32, wn = (warp >> 2) * 64;
    int sw = (g & 1) << 2;

    float c[2][8][4];
#pragma unroll
    for (int mi = 0; mi < 2; mi++)
#pragma unroll
        for (int nj = 0; nj < 8; nj++)
#pragma unroll
            for (int q = 0; q < 4; q++) c[mi][nj][q] = 0.f;

    issue(0, 0);
    asm volatile("cp.async.commit_group;" ::: "memory");
    issue(1, 32);
    asm volatile("cp.async.commit_group;" ::: "memory");

    for (int ki = 0; ki < KT; ki++) {
        asm volatile("cp.async.wait_group 1;" ::: "memory");
        __syncthreads();
        if (ki + 2 < KT) issue((ki + 2) % 3, (ki + 2) * 32);
        asm volatile("cp.async.commit_group;" ::: "memory");

        const float* As = sm + (ki % 3) * 8192;
        const float* Bs = As + 4096;
#pragma unroll
        for (int s = 0; s < 2; s++) {
            unsigned ch = (unsigned)(((s * 4 + tg) ^ sw) << 2);
            float4 av[2][2];
#pragma unroll
            for (int mi = 0; mi < 2; mi++) {
                int r0 = wm + mi * 16 + g;
                av[mi][0] = *(const float4*)(As + r0 * 32 + ch);
                av[mi][1] = *(const float4*)(As + (r0 + 8) * 32 + ch);
            }
            float4 bv[8];
#pragma unroll
            for (int nj = 0; nj < 8; nj++) {
                int rb = wn + nj * 8 + g;
                bv[nj] = *(const float4*)(Bs + rb * 32 + ch);
            }
#pragma unroll
            for (int q = 0; q < 2; q++) {
#pragma unroll
                for (int mi = 0; mi < 2; mi++) {
                    unsigned A[4];
                    A[0] = __float_as_uint(q ? av[mi][0].z : av[mi][0].x);
                    A[1] = __float_as_uint(q ? av[mi][1].z : av[mi][1].x);
                    A[2] = __float_as_uint(q ? av[mi][0].w : av[mi][0].y);
                    A[3] = __float_as_uint(q ? av[mi][1].w : av[mi][1].y);
#pragma unroll
                    for (int nj = 0; nj < 8; nj++) {
                        unsigned B[2];
                        B[0] = __float_as_uint(q ? bv[nj].z : bv[nj].x);
                        B[1] = __float_as_uint(q ? bv[nj].w : bv[nj].y);
                        mma_tf32(c[mi][nj], A, B);
                    }
                }
            }
        }
    }

    // epilogue: c0=(row g, col 2tg) c1=(g,2tg+1) c2=(g+8,2tg) c3=(g+8,2tg+1)
#pragma unroll
    for (int mi = 0; mi < 2; mi++) {
#pragma unroll
        for (int rr = 0; rr < 2; rr++) {
            int mloc = wm + mi * 16 + g + rr * 8;
            if (m0 + mloc >= cnt) continue;
            if (MODE == 0) {
                float* hrow = g_h + (size_t)(off + m0 + mloc) * FFD + n0;
#pragma unroll
                for (int nj = 0; nj < 8; nj++) {
                    int n = wn + nj * 8 + 2 * tg;
                    float v0 = c[mi][nj][rr * 2 + 0] + s_bias[n];
                    float v1 = c[mi][nj][rr * 2 + 1] + s_bias[n + 1];
                    v0 = v0 > 0.f ? v0 : 0.1f * v0;
                    v1 = v1 > 0.f ? v1 : 0.1f * v1;
                    float2 hv = make_float2(rtf(v0), rtf(v1));
                    *(float2*)(hrow + n) = hv;
                }
            } else {
                int tok = s_tok[mloc];
                float gt = s_gate[mloc];
                float* orow = out + (size_t)tok * DIM + n0;
#pragma unroll
                for (int nj = 0; nj < 8; nj++) {
                    int n = wn + nj * 8 + 2 * tg;
                    atomicAdd(orow + n,     (c[mi][nj][rr * 2 + 0] + s_bias[n]) * gt);
                    atomicAdd(orow + n + 1, (c[mi][nj][rr * 2 + 1] + s_bias[n + 1]) * gt);
                }
            }
        }
    }
}

extern "C" void kernel_launch(void* const* d_in, const int* in_sizes, int n_in,
                              void* d_out, int out_size) {
    const float* x  = (const float*)d_in[0];
    const float* wg = (const float*)d_in[1];
    const float* bg = (const float*)d_in[2];
    const float* w1 = (const float*)d_in[3];
    const float* b1 = (const float*)d_in[4];
    const float* w2 = (const float*)d_in[5];
    const float* b2 = (const float*)d_in[6];
    float* out = (float*)d_out;

    const int base = T_TOK * DIM;
    int has_tail = (out_size >= base + 4 * T_TOK) ? 1 : 0;

    const int SMEM_BYTES = (3 * 8192 + 384) * 4;
    cudaFuncSetAttribute(k_gemm<0>, cudaFuncAttributeMaxDynamicSharedMemorySize, SMEM_BYTES);
    cudaFuncSetAttribute(k_gemm<1>, cudaFuncAttributeMaxDynamicSharedMemorySize, SMEM_BYTES);

    float* xr;  cudaGetSymbolAddress((void**)&xr,  g_xr);
    float* w1r; cudaGetSymbolAddress((void**)&w1r, g_w1r);
    float* w2r; cudaGetSymbolAddress((void**)&w2r, g_w2r);

    k_zero<<<(out_size + 255) / 256, 256>>>(out, out_size);

    const int n4x = T_TOK * DIM / 4;
    const int n4w = NEXP * FFD * DIM / 4;
    k_round<<<(n4x + 255) / 256, 256>>>((const float4*)x,  (float4*)xr,  n4x);
    k_round<<<(n4w + 255) / 256, 256>>>((const float4*)w1, (float4*)w1r, n4w);
    k_round<<<(n4w + 255) / 256, 256>>>((const float4*)w2, (float4*)w2r, n4w);

    k_gate<<<T_TOK / 8, 256>>>(x, wg, bg, out, has_tail);
    k_offsets<<<1, 1>>>();

    k_gemm<0><<<dim3(FFD / 128, T_TOK / 128, NEXP), 256, SMEM_BYTES>>>(b1, nullptr);
    k_gemm<1><<<dim3(DIM / 128, T_TOK / 128, NEXP), 256, SMEM_BYTES>>>(b2, out);
}

// round 7
// speedup vs baseline: 3.1096x; 2.0940x over previous
#include <cuda_runtime.h>
#include <cuda_fp16.h>
#include <cstdint>

#define T_TOK 8192
#define DIM   1024
#define FFD   4096
#define NEXP  8

// ---- static device scratch (no allocations) ----
__device__ int    g_count[NEXP];
__device__ int    g_offset[NEXP];
__device__ int    g_tok[NEXP * T_TOK];
__device__ float  g_gate[NEXP * T_TOK];
__device__ __half g_xh[(size_t)T_TOK * DIM];
__device__ __half g_w1h[(size_t)NEXP * FFD * DIM];
__device__ __half g_w2h[(size_t)NEXP * DIM * FFD];
__device__ __half g_hh[(size_t)T_TOK * 2 * FFD];

__device__ __forceinline__ void cpa16(unsigned dst, const void* src) {
    asm volatile("cp.async.cg.shared.global [%0], [%1], 16;" :: "r"(dst), "l"(src) : "memory");
}
__device__ __forceinline__ void ldsm4(unsigned r[4], unsigned addr) {
    asm volatile("ldmatrix.sync.aligned.m8n8.x4.shared.b16 {%0,%1,%2,%3}, [%4];"
                 : "=r"(r[0]), "=r"(r[1]), "=r"(r[2]), "=r"(r[3]) : "r"(addr));
}
__device__ __forceinline__ void mma_f16(float c[4], const unsigned a[4], unsigned b0, unsigned b1) {
    asm volatile(
        "mma.sync.aligned.m16n8k16.row.col.f32.f16.f16.f32 "
        "{%0,%1,%2,%3}, {%4,%5,%6,%7}, {%8,%9}, {%0,%1,%2,%3};"
        : "+f"(c[0]), "+f"(c[1]), "+f"(c[2]), "+f"(c[3])
        : "r"(a[0]), "r"(a[1]), "r"(a[2]), "r"(a[3]), "r"(b0), "r"(b1));
}

// ---- zero output + routing counters ----
__global__ void k_zero(float* p, int n) {
    int i = blockIdx.x * blockDim.x + threadIdx.x;
    if (i < n) p[i] = 0.f;
    if (blockIdx.x == 0 && threadIdx.x < NEXP) g_count[threadIdx.x] = 0;
}

// ---- f32 -> f16 (rne) conversion, 8 elems/thread ----
__global__ void k_half(const float4* __restrict__ in, uint4* __restrict__ out, int n8) {
    int i = blockIdx.x * blockDim.x + threadIdx.x;
    if (i < n8) {
        float4 a = in[2 * i], b = in[2 * i + 1];
        __half2 h0 = __floats2half2_rn(a.x, a.y);
        __half2 h1 = __floats2half2_rn(a.z, a.w);
        __half2 h2 = __floats2half2_rn(b.x, b.y);
        __half2 h3 = __floats2half2_rn(b.z, b.w);
        uint4 v;
        v.x = *reinterpret_cast<unsigned*>(&h0);
        v.y = *reinterpret_cast<unsigned*>(&h1);
        v.z = *reinterpret_cast<unsigned*>(&h2);
        v.w = *reinterpret_cast<unsigned*>(&h3);
        out[i] = v;
    }
}

// ---- gating: one warp per token ----
__global__ void k_gate(const float* __restrict__ x, const float* __restrict__ wg,
                       const float* __restrict__ bg, float* __restrict__ out, int has_tail) {
    __shared__ float s_wg[NEXP * DIM];
    __shared__ float s_bg[NEXP];
    int tid = threadIdx.x;
    for (int i = tid; i < NEXP * DIM; i += 256) s_wg[i] = wg[i];
    if (tid < NEXP) s_bg[tid] = bg[tid];
    __syncthreads();

    int warp = tid >> 5, lane = tid & 31;
    int t = blockIdx.x * 8 + warp;
    const float* xr = x + (size_t)t * DIM;

    float acc[NEXP];
#pragma unroll
    for (int e = 0; e < NEXP; e++) acc[e] = 0.f;
    for (int d = lane; d < DIM; d += 32) {
        float xv = xr[d];
#pragma unroll
        for (int e = 0; e < NEXP; e++) acc[e] += xv * s_wg[e * DIM + d];
    }
#pragma unroll
    for (int e = 0; e < NEXP; e++) {
#pragma unroll
        for (int o = 16; o > 0; o >>= 1) acc[e] += __shfl_xor_sync(0xffffffffu, acc[e], o);
    }

    if (lane == 0) {
        float p[NEXP];
        float m = -1e30f;
#pragma unroll
        for (int e = 0; e < NEXP; e++) { p[e] = acc[e] + s_bg[e]; m = fmaxf(m, p[e]); }
        float s = 0.f;
#pragma unroll
        for (int e = 0; e < NEXP; e++) { p[e] = expf(p[e] - m); s += p[e]; }
        float inv = 1.f / s;
#pragma unroll
        for (int e = 0; e < NEXP; e++) p[e] *= inv;

        int e1 = 0;
#pragma unroll
        for (int e = 1; e < NEXP; e++) if (p[e] > p[e1]) e1 = e;
        int e2 = (e1 == 0) ? 1 : 0;
#pragma unroll
        for (int e = 0; e < NEXP; e++) if (e != e1 && p[e] > p[e2]) e2 = e;

        int pos1 = atomicAdd(&g_count[e1], 1);
        g_tok[e1 * T_TOK + pos1]  = t;
        g_gate[e1 * T_TOK + pos1] = p[e1];
        int pos2 = atomicAdd(&g_count[e2], 1);
        g_tok[e2 * T_TOK + pos2]  = t;
        g_gate[e2 * T_TOK + pos2] = p[e2];

        if (has_tail) {
            float* tail = out + (size_t)T_TOK * DIM;
            tail[t * 2 + 0] = (float)e1;
            tail[t * 2 + 1] = (float)e2;
            tail[T_TOK * 2 + t * 2 + 0] = p[e1];
            tail[T_TOK * 2 + t * 2 + 1] = p[e2];
        }
    }
}

__global__ void k_offsets() {
    int s = 0;
    for (int e = 0; e < NEXP; e++) { g_offset[e] = s; s += g_count[e]; }
}

// ---- fp16 grouped GEMM: 128x128 CTA tile, BK=64 halfs, 4-stage cp.async ----
// Smem rows of 64 halfs = 128B, 8 chunks of 16B, swizzle chunk' = chunk ^ (row&7).
// Stage = A(16KB) + B(16KB) = 32KB; 4 stages at sm+0, meta at sm+131072.
// MODE 0: A = gathered g_xh, B = g_w1h -> h = f16(leaky(v + b1))
// MODE 1: A = g_hh,          B = g_w2h -> atomicAdd(out, (v + b2) * gate)
template <int MODE>
__global__ void __launch_bounds__(256, 1)
k_g(const float* __restrict__ bias, float* __restrict__ out) {
    constexpr int KD = (MODE == 0) ? DIM : FFD;
    constexpr int ND = (MODE == 0) ? FFD : DIM;
    constexpr int KT = KD / 64;

    int e = blockIdx.z;
    int cnt = g_count[e];
    int m0 = blockIdx.y * 128;
    if (m0 >= cnt) return;
    int n0 = blockIdx.x * 128;
    int off = g_offset[e];

    extern __shared__ __align__(1024) char sm[];
    const unsigned sb = (unsigned)__cvta_generic_to_shared(sm);
    int*   s_tok  = (int*)(sm + 131072);
    float* s_gate = (float*)(sm + 131072 + 512);
    float* s_bias = (float*)(sm + 131072 + 1024);

    int tid = threadIdx.x;
    if (tid < 128) {
        int mc = min(m0 + tid, cnt - 1);
        s_tok[tid]  = g_tok[e * T_TOK + mc];
        s_gate[tid] = g_gate[e * T_TOK + mc];
        s_bias[tid] = bias[(size_t)e * ND + n0 + tid];
    }
    __syncthreads();

    const __half* Wb = ((MODE == 0) ? g_w1h : g_w2h) + (size_t)e * ND * KD;

    // loader: 8 threads/row (16B chunk each), rows tid>>3 + {0,32,64,96}
    int lr = tid >> 3, lc = tid & 7;
    const __half* aP[4];
    const __half* bP[4];
#pragma unroll
    for (int i = 0; i < 4; i++) {
        int r = lr + 32 * i;
        if (MODE == 0)
            aP[i] = g_xh + (size_t)s_tok[r] * DIM + lc * 8;
        else
            aP[i] = g_hh + (size_t)(off + min(m0 + r, cnt - 1)) * FFD + lc * 8;
        bP[i] = Wb + (size_t)(n0 + r) * KD + lc * 8;
    }
    const unsigned soff = (unsigned)(lr * 128 + ((lc ^ (lr & 7)) << 4));

    auto fill = [&](int j) {
        unsigned ab = sb + (unsigned)(j & 3) * 32768u + soff;
        const int k0 = j * 64;
#pragma unroll
        for (int i = 0; i < 4; i++) {
            cpa16(ab + i * 4096, aP[i] + k0);
            cpa16(ab + 16384 + i * 4096, bP[i] + k0);
        }
        asm volatile("cp.async.commit_group;" ::: "memory");
    };

    int warp = tid >> 5, lane = tid & 31;
    int g = lane >> 2, tg = lane & 3;
    int wm = (warp & 3) * 32, wn = (warp >> 2) * 64;
    int sub = lane >> 3, rin = lane & 7;
    int arow[2], brow[4];
#pragma unroll
    for (int mi = 0; mi < 2; mi++) arow[mi] = wm + mi * 16 + ((sub & 1) << 3) + rin;
#pragma unroll
    for (int bj = 0; bj < 4; bj++) brow[bj] = wn + bj * 16 + ((sub >> 1) << 3) + rin;
    int qA = sub >> 1, qB = sub & 1;

    float c[2][8][4];
#pragma unroll
    for (int mi = 0; mi < 2; mi++)
#pragma unroll
        for (int nj = 0; nj < 8; nj++)
#pragma unroll
            for (int q = 0; q < 4; q++) c[mi][nj][q] = 0.f;

    fill(0); fill(1); fill(2);

    for (int ki = 0; ki < KT; ki++) {
        asm volatile("cp.async.wait_group %0;" :: "n"(2) : "memory");
        __syncthreads();
        if (ki + 3 < KT) fill(ki + 3);
        else asm volatile("cp.async.commit_group;" ::: "memory");

        unsigned As = sb + (unsigned)(ki & 3) * 32768u;
        unsigned Bs = As + 16384u;
#pragma unroll
        for (int kc = 0; kc < 4; kc++) {
            unsigned a[2][4], b[4][4];
#pragma unroll
            for (int mi = 0; mi < 2; mi++)
                ldsm4(a[mi], As + arow[mi] * 128 + (((kc * 2 + qA) ^ (arow[mi] & 7)) << 4));
#pragma unroll
            for (int bj = 0; bj < 4; bj++)
                ldsm4(b[bj], Bs + brow[bj] * 128 + (((kc * 2 + qB) ^ (brow[bj] & 7)) << 4));
#pragma unroll
            for (int mi = 0; mi < 2; mi++)
#pragma unroll
                for (int nj = 0; nj < 8; nj++) {
                    const unsigned* bb = b[nj >> 1];
                    if (nj & 1) mma_f16(c[mi][nj], a[mi], bb[2], bb[3]);
                    else        mma_f16(c[mi][nj], a[mi], bb[0], bb[1]);
                }
        }
    }

    // epilogue: c[q]: q0=(row g, col 2tg), q1=(g,2tg+1), q2=(g+8,2tg), q3=(g+8,2tg+1)
#pragma unroll
    for (int mi = 0; mi < 2; mi++) {
#pragma unroll
        for (int rr = 0; rr < 2; rr++) {
            int mloc = wm + mi * 16 + g + rr * 8;
            if (m0 + mloc >= cnt) continue;
            if (MODE == 0) {
                __half* hrow = g_hh + (size_t)(off + m0 + mloc) * FFD + n0;
#pragma unroll
                for (int nj = 0; nj < 8; nj++) {
                    int n = wn + nj * 8 + 2 * tg;
                    float v0 = c[mi][nj][rr * 2 + 0] + s_bias[n];
                    float v1 = c[mi][nj][rr * 2 + 1] + s_bias[n + 1];
                    v0 = v0 > 0.f ? v0 : 0.1f * v0;
                    v1 = v1 > 0.f ? v1 : 0.1f * v1;
                    *(__half2*)(hrow + n) = __floats2half2_rn(v0, v1);
                }
            } else {
                int tok = s_tok[mloc];
                float gt = s_gate[mloc];
                float* orow = out + (size_t)tok * DIM + n0;
#pragma unroll
                for (int nj = 0; nj < 8; nj++) {
                    int n = wn + nj * 8 + 2 * tg;
                    atomicAdd(orow + n,     (c[mi][nj][rr * 2 + 0] + s_bias[n]) * gt);
                    atomicAdd(orow + n + 1, (c[mi][nj][rr * 2 + 1] + s_bias[n + 1]) * gt);
                }
            }
        }
    }
}

extern "C" void kernel_launch(void* const* d_in, const int* in_sizes, int n_in,
                              void* d_out, int out_size) {
    const float* x  = (const float*)d_in[0];
    const float* wg = (const float*)d_in[1];
    const float* bg = (const float*)d_in[2];
    const float* w1 = (const float*)d_in[3];
    const float* b1 = (const float*)d_in[4];
    const float* w2 = (const float*)d_in[5];
    const float* b2 = (const float*)d_in[6];
    float* out = (float*)d_out;

    const int base = T_TOK * DIM;
    int has_tail = (out_size >= base + 4 * T_TOK) ? 1 : 0;

    const int SMEM_BYTES = 4 * 32768 + 2048;
    cudaFuncSetAttribute(k_g<0>, cudaFuncAttributeMaxDynamicSharedMemorySize, SMEM_BYTES);
    cudaFuncSetAttribute(k_g<1>, cudaFuncAttributeMaxDynamicSharedMemorySize, SMEM_BYTES);

    __half* xh;  cudaGetSymbolAddress((void**)&xh,  g_xh);
    __half* w1h; cudaGetSymbolAddress((void**)&w1h, g_w1h);
    __half* w2h; cudaGetSymbolAddress((void**)&w2h, g_w2h);

    k_zero<<<(out_size + 255) / 256, 256>>>(out, out_size);

    const int n8x = T_TOK * DIM / 8;
    const int n8w = NEXP * FFD * DIM / 8;
    k_half<<<(n8x + 255) / 256, 256>>>((const float4*)x,  (uint4*)xh,  n8x);
    k_half<<<(n8w + 255) / 256, 256>>>((const float4*)w1, (uint4*)w1h, n8w);
    k_half<<<(n8w + 255) / 256, 256>>>((const float4*)w2, (uint4*)w2h, n8w);

    k_gate<<<T_TOK / 8, 256>>>(x, wg, bg, out, has_tail);
    k_offsets<<<1, 1>>>();

    k_g<0><<<dim3(FFD / 128, T_TOK / 128, NEXP), 256, SMEM_BYTES>>>(b1, nullptr);
    k_g<1><<<dim3(DIM / 128, T_TOK / 128, NEXP), 256, SMEM_BYTES>>>(b2, out);
}

// round 12
// speedup vs baseline: 3.7463x; 1.2048x over previous
#include <cuda_runtime.h>
#include <cuda_fp16.h>
#include <cstdint>

#define T_TOK 8192
#define DIM   1024
#define FFD   4096
#define NEXP  8

// ---- static device scratch (no allocations) ----
__device__ int    g_count[NEXP];
__device__ int    g_offset[NEXP];
__device__ int    g_tok[NEXP * T_TOK];
__device__ float  g_gate[NEXP * T_TOK];
__device__ __half g_xh[(size_t)T_TOK * DIM];
__device__ __half g_w1h[(size_t)NEXP * FFD * DIM];
__device__ __half g_w2h[(size_t)NEXP * DIM * FFD];
__device__ __half g_hh[(size_t)T_TOK * 2 * FFD];

__device__ __forceinline__ void cpa16(unsigned dst, const void* src) {
    asm volatile("cp.async.cg.shared.global [%0], [%1], 16;" :: "r"(dst), "l"(src) : "memory");
}
__device__ __forceinline__ void ldsm4(unsigned r[4], unsigned addr) {
    asm volatile("ldmatrix.sync.aligned.m8n8.x4.shared.b16 {%0,%1,%2,%3}, [%4];"
                 : "=r"(r[0]), "=r"(r[1]), "=r"(r[2]), "=r"(r[3]) : "r"(addr));
}
__device__ __forceinline__ void mma_f16(float c[4], const unsigned a[4], unsigned b0, unsigned b1) {
    asm volatile(
        "mma.sync.aligned.m16n8k16.row.col.f32.f16.f16.f32 "
        "{%0,%1,%2,%3}, {%4,%5,%6,%7}, {%8,%9}, {%0,%1,%2,%3};"
        : "+f"(c[0]), "+f"(c[1]), "+f"(c[2]), "+f"(c[3])
        : "r"(a[0]), "r"(a[1]), "r"(a[2]), "r"(a[3]), "r"(b0), "r"(b1));
}

// ---- zero output + routing counters ----
__global__ void k_zero(float* p, int n) {
    int i = blockIdx.x * blockDim.x + threadIdx.x;
    if (i < n) p[i] = 0.f;
    if (blockIdx.x == 0 && threadIdx.x < NEXP) g_count[threadIdx.x] = 0;
}

// ---- f32 -> f16 (rne) conversion, 8 elems/thread ----
__global__ void k_half(const float4* __restrict__ in, uint4* __restrict__ out, int n8) {
    int i = blockIdx.x * blockDim.x + threadIdx.x;
    if (i < n8) {
        float4 a = in[2 * i], b = in[2 * i + 1];
        __half2 h0 = __floats2half2_rn(a.x, a.y);
        __half2 h1 = __floats2half2_rn(a.z, a.w);
        __half2 h2 = __floats2half2_rn(b.x, b.y);
        __half2 h3 = __floats2half2_rn(b.z, b.w);
        uint4 v;
        v.x = *reinterpret_cast<unsigned*>(&h0);
        v.y = *reinterpret_cast<unsigned*>(&h1);
        v.z = *reinterpret_cast<unsigned*>(&h2);
        v.w = *reinterpret_cast<unsigned*>(&h3);
        out[i] = v;
    }
}

// ---- gating: one warp per token ----
__global__ void k_gate(const float* __restrict__ x, const float* __restrict__ wg,
                       const float* __restrict__ bg, float* __restrict__ out, int has_tail) {
    __shared__ float s_wg[NEXP * DIM];
    __shared__ float s_bg[NEXP];
    int tid = threadIdx.x;
    for (int i = tid; i < NEXP * DIM; i += 256) s_wg[i] = wg[i];
    if (tid < NEXP) s_bg[tid] = bg[tid];
    __syncthreads();

    int warp = tid >> 5, lane = tid & 31;
    int t = blockIdx.x * 8 + warp;
    const float* xr = x + (size_t)t * DIM;

    float acc[NEXP];
#pragma unroll
    for (int e = 0; e < NEXP; e++) acc[e] = 0.f;
    for (int d = lane; d < DIM; d += 32) {
        float xv = xr[d];
#pragma unroll
        for (int e = 0; e < NEXP; e++) acc[e] += xv * s_wg[e * DIM + d];
    }
#pragma unroll
    for (int e = 0; e < NEXP; e++) {
#pragma unroll
        for (int o = 16; o > 0; o >>= 1) acc[e] += __shfl_xor_sync(0xffffffffu, acc[e], o);
    }

    if (lane == 0) {
        float p[NEXP];
        float m = -1e30f;
#pragma unroll
        for (int e = 0; e < NEXP; e++) { p[e] = acc[e] + s_bg[e]; m = fmaxf(m, p[e]); }
        float s = 0.f;
#pragma unroll
        for (int e = 0; e < NEXP; e++) { p[e] = expf(p[e] - m); s += p[e]; }
        float inv = 1.f / s;
#pragma unroll
        for (int e = 0; e < NEXP; e++) p[e] *= inv;

        int e1 = 0;
#pragma unroll
        for (int e = 1; e < NEXP; e++) if (p[e] > p[e1]) e1 = e;
        int e2 = (e1 == 0) ? 1 : 0;
#pragma unroll
        for (int e = 0; e < NEXP; e++) if (e != e1 && p[e] > p[e2]) e2 = e;

        int pos1 = atomicAdd(&g_count[e1], 1);
        g_tok[e1 * T_TOK + pos1]  = t;
        g_gate[e1 * T_TOK + pos1] = p[e1];
        int pos2 = atomicAdd(&g_count[e2], 1);
        g_tok[e2 * T_TOK + pos2]  = t;
        g_gate[e2 * T_TOK + pos2] = p[e2];

        if (has_tail) {
            float* tail = out + (size_t)T_TOK * DIM;
            tail[t * 2 + 0] = (float)e1;
            tail[t * 2 + 1] = (float)e2;
            tail[T_TOK * 2 + t * 2 + 0] = p[e1];
            tail[T_TOK * 2 + t * 2 + 1] = p[e2];
        }
    }
}

__global__ void k_offsets() {
    int s = 0;
    for (int e = 0; e < NEXP; e++) { g_offset[e] = s; s += g_count[e]; }
}

// ---- fp16 grouped GEMM: 128x128 CTA tile, BK=64 halfs, 3-stage cp.async ----
// 3 stages x 32KB + 2KB meta = 98KB smem -> 2 CTAs/SM (16 warps) for latency hiding.
// Smem rows of 64 halfs = 128B, 8 chunks of 16B, swizzle chunk' = chunk ^ (row&7).
// MODE 0: A = gathered g_xh, B = g_w1h -> h = f16(leaky(v + b1))
// MODE 1: A = g_hh,          B = g_w2h -> atomicAdd(out, (v + b2) * gate)
template <int MODE>
__global__ void __launch_bounds__(256, 2)
k_g(const float* __restrict__ bias, float* __restrict__ out) {
    constexpr int KD = (MODE == 0) ? DIM : FFD;
    constexpr int ND = (MODE == 0) ? FFD : DIM;
    constexpr int KT = KD / 64;

    int e = blockIdx.z;
    int cnt = g_count[e];
    int m0 = blockIdx.y * 128;
    if (m0 >= cnt) return;
    int n0 = blockIdx.x * 128;
    int off = g_offset[e];

    extern __shared__ __align__(1024) char sm[];
    const unsigned sb = (unsigned)__cvta_generic_to_shared(sm);
    int*   s_tok  = (int*)(sm + 98304);
    float* s_gate = (float*)(sm + 98304 + 512);
    float* s_bias = (float*)(sm + 98304 + 1024);

    int tid = threadIdx.x;
    if (tid < 128) {
        int mc = min(m0 + tid, cnt - 1);
        s_tok[tid]  = g_tok[e * T_TOK + mc];
        s_gate[tid] = g_gate[e * T_TOK + mc];
        s_bias[tid] = bias[(size_t)e * ND + n0 + tid];
    }
    __syncthreads();

    const __half* Wb = ((MODE == 0) ? g_w1h : g_w2h) + (size_t)e * ND * KD;

    // loader: 8 threads/row (16B chunk each), rows tid>>3 + {0,32,64,96}
    int lr = tid >> 3, lc = tid & 7;
    const __half* aP[4];
    const __half* bP[4];
#pragma unroll
    for (int i = 0; i < 4; i++) {
        int r = lr + 32 * i;
        if (MODE == 0)
            aP[i] = g_xh + (size_t)s_tok[r] * DIM + lc * 8;
        else
            aP[i] = g_hh + (size_t)(off + min(m0 + r, cnt - 1)) * FFD + lc * 8;
        bP[i] = Wb + (size_t)(n0 + r) * KD + lc * 8;
    }
    const unsigned soff = (unsigned)(lr * 128 + ((lc ^ (lr & 7)) << 4));

    auto fill = [&](int j) {
        unsigned ab = sb + (unsigned)(j % 3) * 32768u + soff;
        const int k0 = j * 64;
#pragma unroll
        for (int i = 0; i < 4; i++) {
            cpa16(ab + i * 4096, aP[i] + k0);
            cpa16(ab + 16384 + i * 4096, bP[i] + k0);
        }
        asm volatile("cp.async.commit_group;" ::: "memory");
    };

    int warp = tid >> 5, lane = tid & 31;
    int g = lane >> 2, tg = lane & 3;
    int wm = (warp & 3) * 32, wn = (warp >> 2) * 64;
    int sub = lane >> 3, rin = lane & 7;
    int arow[2], brow[4];
#pragma unroll
    for (int mi = 0; mi < 2; mi++) arow[mi] = wm + mi * 16 + ((sub & 1) << 3) + rin;
#pragma unroll
    for (int bj = 0; bj < 4; bj++) brow[bj] = wn + bj * 16 + ((sub >> 1) << 3) + rin;
    int qA = sub >> 1, qB = sub & 1;

    float c[2][8][4];
#pragma unroll
    for (int mi = 0; mi < 2; mi++)
#pragma unroll
        for (int nj = 0; nj < 8; nj++)
#pragma unroll
            for (int q = 0; q < 4; q++) c[mi][nj][q] = 0.f;

    fill(0); fill(1);

    for (int ki = 0; ki < KT; ki++) {
        asm volatile("cp.async.wait_group %0;" :: "n"(1) : "memory");
        __syncthreads();
        if (ki + 2 < KT) fill(ki + 2);
        else asm volatile("cp.async.commit_group;" ::: "memory");

        unsigned As = sb + (unsigned)(ki % 3) * 32768u;
        unsigned Bs = As + 16384u;
#pragma unroll
        for (int kc = 0; kc < 4; kc++) {
            unsigned a[2][4], b[4][4];
#pragma unroll
            for (int mi = 0; mi < 2; mi++)
                ldsm4(a[mi], As + arow[mi] * 128 + (((kc * 2 + qA) ^ (arow[mi] & 7)) << 4));
#pragma unroll
            for (int bj = 0; bj < 4; bj++)
                ldsm4(b[bj], Bs + brow[bj] * 128 + (((kc * 2 + qB) ^ (brow[bj] & 7)) << 4));
#pragma unroll
            for (int mi = 0; mi < 2; mi++)
#pragma unroll
                for (int nj = 0; nj < 8; nj++) {
                    const unsigned* bb = b[nj >> 1];
                    if (nj & 1) mma_f16(c[mi][nj], a[mi], bb[2], bb[3]);
                    else        mma_f16(c[mi][nj], a[mi], bb[0], bb[1]);
                }
        }
    }

    // epilogue: c[q]: q0=(row g, col 2tg), q1=(g,2tg+1), q2=(g+8,2tg), q3=(g+8,2tg+1)
#pragma unroll
    for (int mi = 0; mi < 2; mi++) {
#pragma unroll
        for (int rr = 0; rr < 2; rr++) {
            int mloc = wm + mi * 16 + g + rr * 8;
            if (m0 + mloc >= cnt) continue;
            if (MODE == 0) {
                __half* hrow = g_hh + (size_t)(off + m0 + mloc) * FFD + n0;
#pragma unroll
                for (int nj = 0; nj < 8; nj++) {
                    int n = wn + nj * 8 + 2 * tg;
                    float v0 = c[mi][nj][rr * 2 + 0] + s_bias[n];
                    float v1 = c[mi][nj][rr * 2 + 1] + s_bias[n + 1];
                    v0 = v0 > 0.f ? v0 : 0.1f * v0;
                    v1 = v1 > 0.f ? v1 : 0.1f * v1;
                    *(__half2*)(hrow + n) = __floats2half2_rn(v0, v1);
                }
            } else {
                int tok = s_tok[mloc];
                float gt = s_gate[mloc];
                float* orow = out + (size_t)tok * DIM + n0;
#pragma unroll
                for (int nj = 0; nj < 8; nj++) {
                    int n = wn + nj * 8 + 2 * tg;
                    atomicAdd(orow + n,     (c[mi][nj][rr * 2 + 0] + s_bias[n]) * gt);
                    atomicAdd(orow + n + 1, (c[mi][nj][rr * 2 + 1] + s_bias[n + 1]) * gt);
                }
            }
        }
    }
}

extern "C" void kernel_launch(void* const* d_in, const int* in_sizes, int n_in,
                              void* d_out, int out_size) {
    const float* x  = (const float*)d_in[0];
    const float* wg = (const float*)d_in[1];
    const float* bg = (const float*)d_in[2];
    const float* w1 = (const float*)d_in[3];
    const float* b1 = (const float*)d_in[4];
    const float* w2 = (const float*)d_in[5];
    const float* b2 = (const float*)d_in[6];
    float* out = (float*)d_out;

    const int base = T_TOK * DIM;
    int has_tail = (out_size >= base + 4 * T_TOK) ? 1 : 0;

    const int SMEM_BYTES = 3 * 32768 + 2048;
    cudaFuncSetAttribute(k_g<0>, cudaFuncAttributeMaxDynamicSharedMemorySize, SMEM_BYTES);
    cudaFuncSetAttribute(k_g<1>, cudaFuncAttributeMaxDynamicSharedMemorySize, SMEM_BYTES);

    __half* xh;  cudaGetSymbolAddress((void**)&xh,  g_xh);
    __half* w1h; cudaGetSymbolAddress((void**)&w1h, g_w1h);
    __half* w2h; cudaGetSymbolAddress((void**)&w2h, g_w2h);

    k_zero<<<(out_size + 255) / 256, 256>>>(out, out_size);

    const int n8x = T_TOK * DIM / 8;
    const int n8w = NEXP * FFD * DIM / 8;
    k_half<<<(n8x + 255) / 256, 256>>>((const float4*)x,  (uint4*)xh,  n8x);
    k_half<<<(n8w + 255) / 256, 256>>>((const float4*)w1, (uint4*)w1h, n8w);
    k_half<<<(n8w + 255) / 256, 256>>>((const float4*)w2, (uint4*)w2h, n8w);

    k_gate<<<T_TOK / 8, 256>>>(x, wg, bg, out, has_tail);
    k_offsets<<<1, 1>>>();

    k_g<0><<<dim3(FFD / 128, T_TOK / 128, NEXP), 256, SMEM_BYTES>>>(b1, nullptr);
    k_g<1><<<dim3(DIM / 128, T_TOK / 128, NEXP), 256, SMEM_BYTES>>>(b2, out);
}

// round 14
// speedup vs baseline: 3.8575x; 1.0297x over previous
#include <cuda_runtime.h>
#include <cuda_fp16.h>
#include <cstdint>

#define T_TOK 8192
#define DIM   1024
#define FFD   4096
#define NEXP  8

// ---- static device scratch (no allocations) ----
__device__ int    g_count[NEXP];
__device__ int    g_offset[NEXP];
__device__ int    g_tok[NEXP * T_TOK];
__device__ float  g_gate[NEXP * T_TOK];
__device__ __half g_xh[(size_t)T_TOK * DIM];
__device__ __half g_w1h[(size_t)NEXP * FFD * DIM];
__device__ __half g_w2h[(size_t)NEXP * DIM * FFD];
__device__ __half g_hh[(size_t)T_TOK * 2 * FFD];

__device__ __forceinline__ void cpa16(unsigned dst, const void* src) {
    asm volatile("cp.async.cg.shared.global [%0], [%1], 16;" :: "r"(dst), "l"(src) : "memory");
}
__device__ __forceinline__ void ldsm4(unsigned r[4], unsigned addr) {
    asm volatile("ldmatrix.sync.aligned.m8n8.x4.shared.b16 {%0,%1,%2,%3}, [%4];"
                 : "=r"(r[0]), "=r"(r[1]), "=r"(r[2]), "=r"(r[3]) : "r"(addr));
}
__device__ __forceinline__ void mma_f16(float c[4], const unsigned a[4], unsigned b0, unsigned b1) {
    asm volatile(
        "mma.sync.aligned.m16n8k16.row.col.f32.f16.f16.f32 "
        "{%0,%1,%2,%3}, {%4,%5,%6,%7}, {%8,%9}, {%0,%1,%2,%3};"
        : "+f"(c[0]), "+f"(c[1]), "+f"(c[2]), "+f"(c[3])
        : "r"(a[0]), "r"(a[1]), "r"(a[2]), "r"(a[3]), "r"(b0), "r"(b1));
}
__device__ __forceinline__ void red2(float* p, float v0, float v1) {
    asm volatile("red.global.add.v2.f32 [%0], {%1, %2};" :: "l"(p), "f"(v0), "f"(v1) : "memory");
}

// ---- init routing counters ----
__global__ void k_init() {
    if (threadIdx.x < NEXP) g_count[threadIdx.x] = 0;
}

// block ranges inside k_prep
#define NB_W1   16384                       // w1 -> fp16   (8 elems/thread)
#define NB_W2   16384                       // w2 -> fp16
#define NB_X    4096                        // x  -> fp16
#define NB_GATE 1024                        // gating, 8 tokens/block

__device__ __forceinline__ void cvt8(const float4* in, uint4* out, int i) {
    float4 a = in[2 * i], b = in[2 * i + 1];
    __half2 h0 = __floats2half2_rn(a.x, a.y);
    __half2 h1 = __floats2half2_rn(a.z, a.w);
    __half2 h2 = __floats2half2_rn(b.x, b.y);
    __half2 h3 = __floats2half2_rn(b.z, b.w);
    uint4 v;
    v.x = *reinterpret_cast<unsigned*>(&h0);
    v.y = *reinterpret_cast<unsigned*>(&h1);
    v.z = *reinterpret_cast<unsigned*>(&h2);
    v.w = *reinterpret_cast<unsigned*>(&h3);
    out[i] = v;
}

// ---- fused prep: weight/x fp16 conversion + out zero + gating, one launch ----
__global__ void __launch_bounds__(256)
k_prep(const float* __restrict__ x, const float* __restrict__ wg,
       const float* __restrict__ bg, const float* __restrict__ w1,
       const float* __restrict__ w2, float* __restrict__ out,
       int out_size, int has_tail, int nb_zero) {
    __shared__ float s_wg[NEXP * DIM];
    __shared__ float s_bg[NEXP];
    int b = blockIdx.x, tid = threadIdx.x;

    if (b < NB_W1) {
        cvt8((const float4*)w1, (uint4*)g_w1h, b * 256 + tid);
        return;
    }
    b -= NB_W1;
    if (b < NB_W2) {
        cvt8((const float4*)w2, (uint4*)g_w2h, b * 256 + tid);
        return;
    }
    b -= NB_W2;
    if (b < NB_X) {
        cvt8((const float4*)x, (uint4*)g_xh, b * 256 + tid);
        return;
    }
    b -= NB_X;
    if (b < nb_zero) {
        int i4 = b * 256 + tid;
        int i = i4 * 4;
        if (i < out_size) {
            const int base = T_TOK * DIM;
            // skip tail region [base, base+4T) when gate writes it
            if (!(has_tail && i >= base && i < base + 4 * T_TOK))
                *(float4*)(out + i) = make_float4(0.f, 0.f, 0.f, 0.f);
        }
        return;
    }
    b -= nb_zero;

    // ---- gating: one warp per token, 8 tokens per block ----
    for (int i = tid; i < NEXP * DIM; i += 256) s_wg[i] = wg[i];
    if (tid < NEXP) s_bg[tid] = bg[tid];
    __syncthreads();

    int warp = tid >> 5, lane = tid & 31;
    int t = b * 8 + warp;
    const float* xr = x + (size_t)t * DIM;

    float acc[NEXP];
#pragma unroll
    for (int e = 0; e < NEXP; e++) acc[e] = 0.f;
    for (int d = lane; d < DIM; d += 32) {
        float xv = xr[d];
#pragma unroll
        for (int e = 0; e < NEXP; e++) acc[e] += xv * s_wg[e * DIM + d];
    }
#pragma unroll
    for (int e = 0; e < NEXP; e++) {
#pragma unroll
        for (int o = 16; o > 0; o >>= 1) acc[e] += __shfl_xor_sync(0xffffffffu, acc[e], o);
    }

    if (lane == 0) {
        float p[NEXP];
        float m = -1e30f;
#pragma unroll
        for (int e = 0; e < NEXP; e++) { p[e] = acc[e] + s_bg[e]; m = fmaxf(m, p[e]); }
        float s = 0.f;
#pragma unroll
        for (int e = 0; e < NEXP; e++) { p[e] = expf(p[e] - m); s += p[e]; }
        float inv = 1.f / s;
#pragma unroll
        for (int e = 0; e < NEXP; e++) p[e] *= inv;

        int e1 = 0;
#pragma unroll
        for (int e = 1; e < NEXP; e++) if (p[e] > p[e1]) e1 = e;
        int e2 = (e1 == 0) ? 1 : 0;
#pragma unroll
        for (int e = 0; e < NEXP; e++) if (e != e1 && p[e] > p[e2]) e2 = e;

        int pos1 = atomicAdd(&g_count[e1], 1);
        g_tok[e1 * T_TOK + pos1]  = t;
        g_gate[e1 * T_TOK + pos1] = p[e1];
        int pos2 = atomicAdd(&g_count[e2], 1);
        g_tok[e2 * T_TOK + pos2]  = t;
        g_gate[e2 * T_TOK + pos2] = p[e2];

        if (has_tail) {
            float* tail = out + (size_t)T_TOK * DIM;
            tail[t * 2 + 0] = (float)e1;
            tail[t * 2 + 1] = (float)e2;
            tail[T_TOK * 2 + t * 2 + 0] = p[e1];
            tail[T_TOK * 2 + t * 2 + 1] = p[e2];
        }
    }
}

__global__ void k_offsets() {
    int s = 0;
    for (int e = 0; e < NEXP; e++) { g_offset[e] = s; s += g_count[e]; }
}

// ---- fp16 grouped GEMM: 128x128 CTA tile, BK=64 halfs, 3-stage cp.async ----
// 3 stages x 32KB + 2KB meta = 98KB smem -> 2 CTAs/SM (16 warps) for latency hiding.
// Smem rows of 64 halfs = 128B, 8 chunks of 16B, swizzle chunk' = chunk ^ (row&7).
// MODE 0: A = gathered g_xh, B = g_w1h -> h = f16(leaky(v + b1))
// MODE 1: A = g_hh,          B = g_w2h -> red.v2(out, (v + b2) * gate)
template <int MODE>
__global__ void __launch_bounds__(256, 2)
k_g(const float* __restrict__ bias, float* __restrict__ out) {
    constexpr int KD = (MODE == 0) ? DIM : FFD;
    constexpr int ND = (MODE == 0) ? FFD : DIM;
    constexpr int KT = KD / 64;

    int e = blockIdx.z;
    int cnt = g_count[e];
    int m0 = blockIdx.y * 128;
    if (m0 >= cnt) return;
    int n0 = blockIdx.x * 128;
    int off = g_offset[e];

    extern __shared__ __align__(1024) char sm[];
    const unsigned sb = (unsigned)__cvta_generic_to_shared(sm);
    int*   s_tok  = (int*)(sm + 98304);
    float* s_gate = (float*)(sm + 98304 + 512);
    float* s_bias = (float*)(sm + 98304 + 1024);

    int tid = threadIdx.x;
    if (tid < 128) {
        int mc = min(m0 + tid, cnt - 1);
        s_tok[tid]  = g_tok[e * T_TOK + mc];
        s_gate[tid] = g_gate[e * T_TOK + mc];
        s_bias[tid] = bias[(size_t)e * ND + n0 + tid];
    }
    __syncthreads();

    const __half* Wb = ((MODE == 0) ? g_w1h : g_w2h) + (size_t)e * ND * KD;

    // loader: 8 threads/row (16B chunk each), rows tid>>3 + {0,32,64,96}
    int lr = tid >> 3, lc = tid & 7;
    const __half* aP[4];
    const __half* bP[4];
#pragma unroll
    for (int i = 0; i < 4; i++) {
        int r = lr + 32 * i;
        if (MODE == 0)
            aP[i] = g_xh + (size_t)s_tok[r] * DIM + lc * 8;
        else
            aP[i] = g_hh + (size_t)(off + min(m0 + r, cnt - 1)) * FFD + lc * 8;
        bP[i] = Wb + (size_t)(n0 + r) * KD + lc * 8;
    }
    const unsigned soff = (unsigned)(lr * 128 + ((lc ^ (lr & 7)) << 4));

    auto fill = [&](int j) {
        unsigned ab = sb + (unsigned)(j % 3) * 32768u + soff;
        const int k0 = j * 64;
#pragma unroll
        for (int i = 0; i < 4; i++) {
            cpa16(ab + i * 4096, aP[i] + k0);
            cpa16(ab + 16384 + i * 4096, bP[i] + k0);
        }
        asm volatile("cp.async.commit_group;" ::: "memory");
    };

    int warp = tid >> 5, lane = tid & 31;
    int g = lane >> 2, tg = lane & 3;
    int wm = (warp & 3) * 32, wn = (warp >> 2) * 64;
    int sub = lane >> 3, rin = lane & 7;
    int arow[2], brow[4];
#pragma unroll
    for (int mi = 0; mi < 2; mi++) arow[mi] = wm + mi * 16 + ((sub & 1) << 3) + rin;
#pragma unroll
    for (int bj = 0; bj < 4; bj++) brow[bj] = wn + bj * 16 + ((sub >> 1) << 3) + rin;
    int qA = sub >> 1, qB = sub & 1;

    float c[2][8][4];
#pragma unroll
    for (int mi = 0; mi < 2; mi++)
#pragma unroll
        for (int nj = 0; nj < 8; nj++)
#pragma unroll
            for (int q = 0; q < 4; q++) c[mi][nj][q] = 0.f;

    fill(0); fill(1);

    for (int ki = 0; ki < KT; ki++) {
        asm volatile("cp.async.wait_group %0;" :: "n"(1) : "memory");
        __syncthreads();
        if (ki + 2 < KT) fill(ki + 2);
        else asm volatile("cp.async.commit_group;" ::: "memory");

        unsigned As = sb + (unsigned)(ki % 3) * 32768u;
        unsigned Bs = As + 16384u;
#pragma unroll
        for (int kc = 0; kc < 4; kc++) {
            unsigned a[2][4], b[4][4];
#pragma unroll
            for (int mi = 0; mi < 2; mi++)
                ldsm4(a[mi], As + arow[mi] * 128 + (((kc * 2 + qA) ^ (arow[mi] & 7)) << 4));
#pragma unroll
            for (int bj = 0; bj < 4; bj++)
                ldsm4(b[bj], Bs + brow[bj] * 128 + (((kc * 2 + qB) ^ (brow[bj] & 7)) << 4));
#pragma unroll
            for (int mi = 0; mi < 2; mi++)
#pragma unroll
                for (int nj = 0; nj < 8; nj++) {
                    const unsigned* bb = b[nj >> 1];
                    if (nj & 1) mma_f16(c[mi][nj], a[mi], bb[2], bb[3]);
                    else        mma_f16(c[mi][nj], a[mi], bb[0], bb[1]);
                }
        }
    }

    // epilogue: c[q]: q0=(row g, col 2tg), q1=(g,2tg+1), q2=(g+8,2tg), q3=(g+8,2tg+1)
#pragma unroll
    for (int mi = 0; mi < 2; mi++) {
#pragma unroll
        for (int rr = 0; rr < 2; rr++) {
            int mloc = wm + mi * 16 + g + rr * 8;
            if (m0 + mloc >= cnt) continue;
            if (MODE == 0) {
                __half* hrow = g_hh + (size_t)(off + m0 + mloc) * FFD + n0;
#pragma unroll
                for (int nj = 0; nj < 8; nj++) {
                    int n = wn + nj * 8 + 2 * tg;
                    float v0 = c[mi][nj][rr * 2 + 0] + s_bias[n];
                    float v1 = c[mi][nj][rr * 2 + 1] + s_bias[n + 1];
                    v0 = v0 > 0.f ? v0 : 0.1f * v0;
                    v1 = v1 > 0.f ? v1 : 0.1f * v1;
                    *(__half2*)(hrow + n) = __floats2half2_rn(v0, v1);
                }
            } else {
                int tok = s_tok[mloc];
                float gt = s_gate[mloc];
                float* orow = out + (size_t)tok * DIM + n0;
#pragma unroll
                for (int nj = 0; nj < 8; nj++) {
                    int n = wn + nj * 8 + 2 * tg;
                    red2(orow + n, (c[mi][nj][rr * 2 + 0] + s_bias[n]) * gt,
                                   (c[mi][nj][rr * 2 + 1] + s_bias[n + 1]) * gt);
                }
            }
        }
    }
}

extern "C" void kernel_launch(void* const* d_in, const int* in_sizes, int n_in,
                              void* d_out, int out_size) {
    const float* x  = (const float*)d_in[0];
    const float* wg = (const float*)d_in[1];
    const float* bg = (const float*)d_in[2];
    const float* w1 = (const float*)d_in[3];
    const float* b1 = (const float*)d_in[4];
    const float* w2 = (const float*)d_in[5];
    const float* b2 = (const float*)d_in[6];
    float* out = (float*)d_out;

    const int base = T_TOK * DIM;
    int has_tail = (out_size >= base + 4 * T_TOK) ? 1 : 0;
    int nb_zero = (out_size / 4 + 255) / 256;

    const int SMEM_BYTES = 3 * 32768 + 2048;
    cudaFuncSetAttribute(k_g<0>, cudaFuncAttributeMaxDynamicSharedMemorySize, SMEM_BYTES);
    cudaFuncSetAttribute(k_g<1>, cudaFuncAttributeMaxDynamicSharedMemorySize, SMEM_BYTES);

    k_init<<<1, 32>>>();
    k_prep<<<NB_W1 + NB_W2 + NB_X + nb_zero + NB_GATE, 256>>>(
        x, wg, bg, w1, w2, out, out_size, has_tail, nb_zero);
    k_offsets<<<1, 1>>>();

    k_g<0><<<dim3(FFD / 128, T_TOK / 128, NEXP), 256, SMEM_BYTES>>>(b1, nullptr);
    k_g<1><<<dim3(DIM / 128, T_TOK / 128, NEXP), 256, SMEM_BYTES>>>(b2, out);
}